// round 14
// baseline (speedup 1.0000x reference)
#include <cuda_runtime.h>
#include <cuda_fp16.h>
#include <mma.h>

using namespace nvcuda;

#define NN 100000
#define NE 1200000
#define NCSR (NE + NN)                // edges + self-loops
#define NF 64
#define NH 256
#define NC 40
#define NITER 8
#define NSCAN 196                     // ceil(NN/512) scan tiles
#define NDEG 1024                     // degree bins for counting sort

// ---------------- scratch (device globals; no allocation) ----------------
__device__ int   g_cnt[NN];
__device__ float g_dinv[NN];
__device__ int   g_rowptr[NN + 1];
__device__ int   g_cursor[NN];
__device__ int   g_degcnt[NDEG];
__device__ int   g_degoff[NDEG];
__device__ unsigned long long g_tile_state[NSCAN];  // (status<<32)|sum; 1=agg,2=prefix
__device__ int   g_tile_counter;
__device__ __align__(16) int4    g_task[NN];        // {start, len, row*32, 0} sorted by degree
__device__ __align__(16) int2    g_csr[NCSR];       // {col*32, w as half2 bits}
// h0..h8 in fp16: (9 * 100000 * 32) half2 = 115 MB. Row = 32 half2 = 128 B.
__device__ __align__(16) __half2 g_hh[(NITER + 1) * (size_t)NN * (NF / 2)];

__device__ __forceinline__ int clampN(int v) {
    return min(max(v, 0), NN - 1);
}

// ---------------- L1: histogram (+ reset per-run state) ----------
__global__ void k_hist(const int* __restrict__ ei) {
    int e = blockIdx.x * blockDim.x + threadIdx.x;
    if (e < NE) atomicAdd(&g_cnt[clampN(ei[e])], 1);
    if (e < NSCAN) g_tile_state[e] = 0ULL;
    if (e < NDEG)  g_degcnt[e] = 0;
    if (e == NSCAN) g_tile_counter = 0;
}

// ---------------- L2: decoupled-lookback scan + dinv + deg-hist + h0 init --
__global__ void __launch_bounds__(512) k_scan_init(const float* __restrict__ x) {
    if (blockIdx.x < NSCAN) {
        __shared__ int s[512];
        __shared__ int stile;
        __shared__ int sprefix;
        int t = threadIdx.x;
        if (t == 0) stile = atomicAdd(&g_tile_counter, 1);
        __syncthreads();
        int tile = stile;
        int i = tile * 512 + t;
        int deg = (i < NN) ? g_cnt[i] : 0;
        int v   = (i < NN) ? deg + 1 : 0;     // +1 self-loop slot
        if (i < NN) {
            g_dinv[i] = rsqrtf((float)(deg + 1));
            atomicAdd(&g_degcnt[min(deg, NDEG - 1)], 1);
        }
        s[t] = v;
        __syncthreads();
        for (int off = 1; off < 512; off <<= 1) {
            int add = (t >= off) ? s[t - off] : 0;
            __syncthreads();
            s[t] += add;
            __syncthreads();
        }
        int incl = s[t];
        int agg  = s[511];
        if (t == 0) {
            if (tile == 0) {
                atomicExch(&g_tile_state[0], (2ULL << 32) | (unsigned)agg);
                sprefix = 0;
            } else {
                atomicExch(&g_tile_state[tile], (1ULL << 32) | (unsigned)agg);
                int pre = 0;
                for (int p = tile - 1; p >= 0; ) {
                    unsigned long long st;
                    do { st = atomicAdd(&g_tile_state[p], 0ULL); } while ((st >> 32) == 0);
                    pre += (int)(unsigned)st;
                    if ((st >> 32) == 2ULL) break;
                    p--;
                }
                atomicExch(&g_tile_state[tile], (2ULL << 32) | (unsigned)(pre + agg));
                sprefix = pre;
            }
        }
        __syncthreads();
        if (i < NN) {
            int rp = sprefix + incl - v;   // exclusive
            g_rowptr[i] = rp;
            g_cursor[i] = rp;
        }
        if (tile == 0 && t == 0) g_rowptr[NN] = NCSR;
    } else {
        int i = (blockIdx.x - NSCAN) * 512 + threadIdx.x;   // quad of 4 floats
        if (i < NN * (NF / 4)) {
            float4 v = ((const float4*)x)[i];
            __half2 a = __floats2half2_rn(v.x * 0.5f, v.y * 0.5f);
            __half2 b = __floats2half2_rn(v.z * 0.5f, v.w * 0.5f);
            *(uint2*)&g_hh[(size_t)i * 2] =
                make_uint2(*(unsigned*)&a, *(unsigned*)&b);
        }
    }
}

// ---------------- L2b: exclusive scan of 1024 degree bins (1 block) --------
__global__ void __launch_bounds__(1024) k_degscan() {
    __shared__ int s[NDEG];
    int t = threadIdx.x;
    int v = g_degcnt[t];
    s[t] = v;
    __syncthreads();
    for (int off = 1; off < NDEG; off <<= 1) {
        int add = (t >= off) ? s[t - off] : 0;
        __syncthreads();
        s[t] += add;
        __syncthreads();
    }
    g_degoff[t] = s[t] - v;   // exclusive
}

// ---------------- L3: scatter edges + self-loops + task build + re-zero ----
__global__ void k_scatter(const int* __restrict__ ei) {
    int e = blockIdx.x * blockDim.x + threadIdx.x;
    if (e < NE) {
        int r = clampN(ei[e]);
        int c = clampN(ei[NE + e]);
        int pos = atomicAdd(&g_cursor[r], 1);
        __half2 wh = __float2half2_rn(g_dinv[r] * g_dinv[c]);
        g_csr[pos] = make_int2(c * 32, *reinterpret_cast<int*>(&wh));
    }
    if (e < NN) {
        float dr = g_dinv[e];
        int pos = atomicAdd(&g_cursor[e], 1);
        __half2 wh = __float2half2_rn(dr * dr);
        g_csr[pos] = make_int2(e * 32, *reinterpret_cast<int*>(&wh));
        int d = g_cnt[e];
        int p = atomicAdd(&g_degoff[min(d, NDEG - 1)], 1);
        int start = g_rowptr[e];
        int len   = g_rowptr[e + 1] - start;   // = deg+1
        g_task[p] = make_int4(start, len, e * 32, 0);
        g_cnt[e] = 0;
    }
}

// ---------------- SPMM: h_{it+1} = A_norm h_it ------------------------------
// 4 rows/warp (degree-sorted tasks), 8-lane group per row, lane = 8 features.
// Register diet: single fp16 chain (4 half2), min-7-blocks launch bound ->
// higher occupancy for this latency-bound kernel.
__global__ void __launch_bounds__(256, 7) k_spmm(int it) {
    const size_t NN32 = (size_t)NN * (NF / 2);
    const __half2* __restrict__ hin = g_hh + (size_t)it * NN32;
    __half2* __restrict__ hout      = g_hh + (size_t)(it + 1) * NN32;

    __shared__ int2 se[8][4][17];    // [warp][group][slot], padded

    int lane = threadIdx.x & 31;
    int wid  = threadIdx.x >> 5;
    int g    = lane >> 3;            // group 0..3
    int li   = lane & 7;             // lane in group

    int4 task = __ldg(&g_task[(blockIdx.x * 8 + wid) * 4 + g]);  // NN div by 32
    int start = task.x;
    int len   = task.y;
    int end   = start + len;
    int row32 = task.z;

    float accf[8] = {0.f, 0.f, 0.f, 0.f, 0.f, 0.f, 0.f, 0.f};

    // uniform loop bound over the 4 groups (sorted rows -> nearly equal)
    int m1   = max(len, __shfl_xor_sync(0xffffffffu, len, 8));
    int mlen = max(m1,  __shfl_xor_sync(0xffffffffu, m1, 16));

    const __half2 z2 = __float2half2_rn(0.f);

    for (int b = 0; b < mlen; b += 16) {
        int idx0 = start + b + li;
        int idx1 = idx0 + 8;
        int2 e0 = (idx0 < end) ? g_csr[idx0] : make_int2(0, 0);
        int2 e1 = (idx1 < end) ? g_csr[idx1] : make_int2(0, 0);
        se[wid][g][li]     = e0;
        se[wid][g][li + 8] = e1;
        __syncwarp();

        __half2 a0 = z2, a1 = z2, a2 = z2, a3 = z2;   // single chain, <=16 adds
#pragma unroll
        for (int j = 0; j < 16; j++) {                // fixed trip: batched LDGs
            int2    ej = se[wid][g][j];
            __half2 wj = *reinterpret_cast<__half2*>(&ej.y);
            uint4   t  = __ldg((const uint4*)(hin + ej.x + li * 4));
            a0 = __hfma2(wj, *(__half2*)&t.x, a0);
            a1 = __hfma2(wj, *(__half2*)&t.y, a1);
            a2 = __hfma2(wj, *(__half2*)&t.z, a2);
            a3 = __hfma2(wj, *(__half2*)&t.w, a3);
        }
        __syncwarp();

        float2 s0 = __half22float2(a0);
        float2 s1 = __half22float2(a1);
        float2 s2 = __half22float2(a2);
        float2 s3 = __half22float2(a3);
        accf[0] += s0.x; accf[1] += s0.y;
        accf[2] += s1.x; accf[3] += s1.y;
        accf[4] += s2.x; accf[5] += s2.y;
        accf[6] += s3.x; accf[7] += s3.y;
    }

    __half2 r0 = __floats2half2_rn(accf[0], accf[1]);
    __half2 r1 = __floats2half2_rn(accf[2], accf[3]);
    __half2 r2 = __floats2half2_rn(accf[4], accf[5]);
    __half2 r3 = __floats2half2_rn(accf[6], accf[7]);
    uint4 o;
    o.x = *(unsigned*)&r0; o.y = *(unsigned*)&r1;
    o.z = *(unsigned*)&r2; o.w = *(unsigned*)&r3;
    *(uint4*)(hout + row32 + li * 4) = o;
}

// ---------------- fused MLP on tensor cores (wmma m16n16k16, f32 accum) ----
#define LDA 72   // fp16 lds (mult of 8)
#define LDB 48   // W2 cols padded
__global__ void __launch_bounds__(256) k_mlp(const float* __restrict__ W1,
                                             const float* __restrict__ b1,
                                             const float* __restrict__ W2,
                                             const float* __restrict__ b2,
                                             float* __restrict__ out) {
    __shared__ __align__(16) __half AsH[32 * LDA];    // 4.6 KB
    __shared__ __align__(16) __half W1cH[64 * LDA];   // 9.2 KB
    __shared__ __align__(16) float  HsF[32 * LDA];    // 9.2 KB
    __shared__ __align__(16) __half HsH[32 * LDA];    // 4.6 KB
    __shared__ __align__(16) __half W2cH[64 * LDB];   // 6.1 KB
    __shared__ __align__(16) float  OutF[32 * LDB];   // 6.1 KB

    int tid = threadIdx.x;
    int wid = tid >> 5;
    int rb  = blockIdx.x * 32;        // NN divisible by 32

    const float inv = 1.0f / (NITER + 1);
    const size_t NN32 = (size_t)NN * (NF / 2);
    for (int l = tid; l < 32 * 16; l += 256) {   // quads of 4 feats
        int rr = l >> 4, q = l & 15;
        float4 s = make_float4(0.f, 0.f, 0.f, 0.f);
#pragma unroll
        for (int b = 0; b <= NITER; b++) {
            const uint2* hb = (const uint2*)(g_hh + (size_t)b * NN32);
            uint2 v = __ldg(&hb[(size_t)(rb + rr) * 16 + q]);
            float2 f0 = __half22float2(*(__half2*)&v.x);
            float2 f1 = __half22float2(*(__half2*)&v.y);
            s.x += f0.x; s.y += f0.y; s.z += f1.x; s.w += f1.y;
        }
        __half2 p0 = __floats2half2_rn(s.x * inv, s.y * inv);
        __half2 p1 = __floats2half2_rn(s.z * inv, s.w * inv);
        *(uint2*)&AsH[rr * LDA + q * 4] =
            make_uint2(*(unsigned*)&p0, *(unsigned*)&p1);
    }

    wmma::fragment<wmma::accumulator, 16, 16, 16, float> ofrag;
    int omi = wid / 3, oni = wid % 3;   // warps 0..5: out tile (omi, oni)
    if (wid < 6) wmma::fill_fragment(ofrag, 0.f);

    for (int c = 0; c < 4; c++) {
        __syncthreads();
        for (int l = tid; l < 64 * 64; l += 256) {
            int kk = l >> 6, j = l & 63;
            W1cH[kk * LDA + j] = __float2half(__ldg(&W1[kk * NH + c * 64 + j]));
        }
        for (int l = tid; l < 64 * LDB; l += 256) {
            int kk = l / LDB, n = l % LDB;
            W2cH[kk * LDB + n] =
                (n < NC) ? __float2half(__ldg(&W2[(c * 64 + kk) * NC + n]))
                         : __half(0.f);
        }
        __syncthreads();

        {
            int mi = wid >> 2, ni = wid & 3;
            wmma::fragment<wmma::accumulator, 16, 16, 16, float> hfrag;
            wmma::fill_fragment(hfrag, 0.f);
#pragma unroll
            for (int k = 0; k < 4; k++) {
                wmma::fragment<wmma::matrix_a, 16, 16, 16, __half, wmma::row_major> af;
                wmma::fragment<wmma::matrix_b, 16, 16, 16, __half, wmma::row_major> bf;
                wmma::load_matrix_sync(af, &AsH[mi * 16 * LDA + k * 16], LDA);
                wmma::load_matrix_sync(bf, &W1cH[k * 16 * LDA + ni * 16], LDA);
                wmma::mma_sync(hfrag, af, bf, hfrag);
            }
            wmma::store_matrix_sync(&HsF[mi * 16 * LDA + ni * 16], hfrag, LDA,
                                    wmma::mem_row_major);
        }
        __syncthreads();

        for (int l = tid; l < 32 * 64; l += 256) {
            int r = l >> 6, j = l & 63;
            float v = HsF[r * LDA + j] + __ldg(&b1[c * 64 + j]);
            HsH[r * LDA + j] = __float2half(fmaxf(v, 0.f));
        }
        __syncthreads();

        if (wid < 6) {
#pragma unroll
            for (int k = 0; k < 4; k++) {
                wmma::fragment<wmma::matrix_a, 16, 16, 16, __half, wmma::row_major> af;
                wmma::fragment<wmma::matrix_b, 16, 16, 16, __half, wmma::row_major> bf;
                wmma::load_matrix_sync(af, &HsH[omi * 16 * LDA + k * 16], LDA);
                wmma::load_matrix_sync(bf, &W2cH[k * 16 * LDB + oni * 16], LDB);
                wmma::mma_sync(ofrag, af, bf, ofrag);
            }
        }
    }

    __syncthreads();
    if (wid < 6)
        wmma::store_matrix_sync(&OutF[omi * 16 * LDB + oni * 16], ofrag, LDB,
                                wmma::mem_row_major);
    __syncthreads();

    for (int l = tid; l < 32 * NC; l += 256) {
        int r = l / NC, n = l - r * NC;
        out[(size_t)(rb + r) * NC + n] = OutF[r * LDB + n] + __ldg(&b2[n]);
    }
}

// ---------------- launch ----------------
extern "C" void kernel_launch(void* const* d_in, const int* in_sizes, int n_in,
                              void* d_out, int out_size) {
    const float* x   = (const float*)d_in[0];
    const int*   ei  = (const int*)d_in[1];   // int32 (JAX demotes int64)
    const float* W1  = (const float*)d_in[2];
    const float* b1  = (const float*)d_in[3];
    const float* W2  = (const float*)d_in[4];
    const float* b2  = (const float*)d_in[5];
    float*       out = (float*)d_out;

    int init_blocks = (NN * (NF / 4) + 511) / 512;   // 3125

    k_hist<<<(NE + 255) / 256, 256>>>(ei);                     // launch 1
    k_scan_init<<<NSCAN + init_blocks, 512>>>(x);              // launch 2
    k_degscan<<<1, NDEG>>>();                                  // launch 3
    k_scatter<<<(NE + 255) / 256, 256>>>(ei);                  // launch 4

    for (int it = 0; it < NITER; it++)                         // launches 5..12
        k_spmm<<<NN / 32, 256>>>(it);

    k_mlp<<<NN / 32, 256>>>(W1, b1, W2, b2, out);              // launch 13
}

// round 15
// speedup vs baseline: 1.0505x; 1.0505x over previous
#include <cuda_runtime.h>
#include <cuda_fp16.h>
#include <mma.h>

using namespace nvcuda;

#define NN 100000
#define NE 1200000
#define NCSR (NE + NN)                // edges + self-loops
#define NF 64
#define NH 256
#define NC 40
#define NITER 8
#define NSCAN 196                     // ceil(NN/512) scan tiles
#define NDEG 1024                     // degree bins for counting sort

// ---------------- scratch (device globals; no allocation) ----------------
__device__ int   g_cnt[NN];
__device__ float g_dinv[NN];
__device__ int   g_rowptr[NN + 1];
__device__ int   g_cursor[NN];
__device__ int   g_degcnt[NDEG];
__device__ int   g_degoff[NDEG];
__device__ unsigned long long g_tile_state[NSCAN];  // (status<<32)|sum; 1=agg,2=prefix
__device__ int   g_tile_counter;
__device__ __align__(16) int4    g_task[NN];        // {start, len, row*32, 0} DESC degree
__device__ __align__(16) int2    g_csr[NCSR];       // {col*32, w as half2 bits}
// h0..h8 in fp16: (9 * 100000 * 32) half2 = 115 MB. Row = 32 half2 = 128 B.
__device__ __align__(16) __half2 g_hh[(NITER + 1) * (size_t)NN * (NF / 2)];

__device__ __forceinline__ int clampN(int v) {
    return min(max(v, 0), NN - 1);
}

// ---------------- L1: histogram (+ reset per-run state) ----------
__global__ void k_hist(const int* __restrict__ ei) {
    int e = blockIdx.x * blockDim.x + threadIdx.x;
    if (e < NE) atomicAdd(&g_cnt[clampN(ei[e])], 1);
    if (e < NSCAN) g_tile_state[e] = 0ULL;
    if (e < NDEG)  g_degcnt[e] = 0;
    if (e == NSCAN) g_tile_counter = 0;
}

// ---------------- L2: decoupled-lookback scan + dinv + deg-hist + h0 init --
__global__ void __launch_bounds__(512) k_scan_init(const float* __restrict__ x) {
    if (blockIdx.x < NSCAN) {
        __shared__ int s[512];
        __shared__ int stile;
        __shared__ int sprefix;
        int t = threadIdx.x;
        if (t == 0) stile = atomicAdd(&g_tile_counter, 1);
        __syncthreads();
        int tile = stile;
        int i = tile * 512 + t;
        int deg = (i < NN) ? g_cnt[i] : 0;
        int v   = (i < NN) ? deg + 1 : 0;     // +1 self-loop slot
        if (i < NN) {
            g_dinv[i] = rsqrtf((float)(deg + 1));
            atomicAdd(&g_degcnt[min(deg, NDEG - 1)], 1);
        }
        s[t] = v;
        __syncthreads();
        for (int off = 1; off < 512; off <<= 1) {
            int add = (t >= off) ? s[t - off] : 0;
            __syncthreads();
            s[t] += add;
            __syncthreads();
        }
        int incl = s[t];
        int agg  = s[511];
        if (t == 0) {
            if (tile == 0) {
                atomicExch(&g_tile_state[0], (2ULL << 32) | (unsigned)agg);
                sprefix = 0;
            } else {
                atomicExch(&g_tile_state[tile], (1ULL << 32) | (unsigned)agg);
                int pre = 0;
                for (int p = tile - 1; p >= 0; ) {
                    unsigned long long st;
                    do { st = atomicAdd(&g_tile_state[p], 0ULL); } while ((st >> 32) == 0);
                    pre += (int)(unsigned)st;
                    if ((st >> 32) == 2ULL) break;
                    p--;
                }
                atomicExch(&g_tile_state[tile], (2ULL << 32) | (unsigned)(pre + agg));
                sprefix = pre;
            }
        }
        __syncthreads();
        if (i < NN) {
            int rp = sprefix + incl - v;   // exclusive
            g_rowptr[i] = rp;
            g_cursor[i] = rp;
        }
        if (tile == 0 && t == 0) g_rowptr[NN] = NCSR;
    } else {
        int i = (blockIdx.x - NSCAN) * 512 + threadIdx.x;   // quad of 4 floats
        if (i < NN * (NF / 4)) {
            float4 v = ((const float4*)x)[i];
            __half2 a = __floats2half2_rn(v.x * 0.5f, v.y * 0.5f);
            __half2 b = __floats2half2_rn(v.z * 0.5f, v.w * 0.5f);
            *(uint2*)&g_hh[(size_t)i * 2] =
                make_uint2(*(unsigned*)&a, *(unsigned*)&b);
        }
    }
}

// ---------------- L2b: exclusive scan of 1024 degree bins (1 block) --------
__global__ void __launch_bounds__(1024) k_degscan() {
    __shared__ int s[NDEG];
    int t = threadIdx.x;
    int v = g_degcnt[t];
    s[t] = v;
    __syncthreads();
    for (int off = 1; off < NDEG; off <<= 1) {
        int add = (t >= off) ? s[t - off] : 0;
        __syncthreads();
        s[t] += add;
        __syncthreads();
    }
    g_degoff[t] = s[t] - v;   // exclusive
}

// ---------------- L3: scatter edges + self-loops + task build + re-zero ----
// Tasks are written in DESCENDING degree order (heavy rows scheduled first ->
// light rows fill the tail wave).
__global__ void k_scatter(const int* __restrict__ ei) {
    int e = blockIdx.x * blockDim.x + threadIdx.x;
    if (e < NE) {
        int r = clampN(ei[e]);
        int c = clampN(ei[NE + e]);
        int pos = atomicAdd(&g_cursor[r], 1);
        __half2 wh = __float2half2_rn(g_dinv[r] * g_dinv[c]);
        g_csr[pos] = make_int2(c * 32, *reinterpret_cast<int*>(&wh));
    }
    if (e < NN) {
        float dr = g_dinv[e];
        int pos = atomicAdd(&g_cursor[e], 1);
        __half2 wh = __float2half2_rn(dr * dr);
        g_csr[pos] = make_int2(e * 32, *reinterpret_cast<int*>(&wh));
        int d = g_cnt[e];
        int p = atomicAdd(&g_degoff[min(d, NDEG - 1)], 1);
        int start = g_rowptr[e];
        int len   = g_rowptr[e + 1] - start;   // = deg+1
        g_task[NN - 1 - p] = make_int4(start, len, e * 32, 0);   // descending
        g_cnt[e] = 0;
    }
}

// ---------------- SPMM: h_{it+1} = A_norm h_it ------------------------------
// (R13 variant — best measured.) 4 rows/warp (degree-sorted tasks), 8-lane
// group per row, lane = 8 features (uint4). Fixed 16-iter inner loop.
__global__ void __launch_bounds__(256) k_spmm(int it) {
    const size_t NN32 = (size_t)NN * (NF / 2);
    const __half2* __restrict__ hin = g_hh + (size_t)it * NN32;
    __half2* __restrict__ hout      = g_hh + (size_t)(it + 1) * NN32;

    __shared__ int2 se[8][4][17];    // [warp][group][slot], padded

    int lane = threadIdx.x & 31;
    int wid  = threadIdx.x >> 5;
    int g    = lane >> 3;            // group 0..3
    int li   = lane & 7;             // lane in group

    int4 task = __ldg(&g_task[(blockIdx.x * 8 + wid) * 4 + g]);  // NN div by 32
    int start = task.x;
    int len   = task.y;
    int end   = start + len;
    int row32 = task.z;

    float accf[8] = {0.f, 0.f, 0.f, 0.f, 0.f, 0.f, 0.f, 0.f};

    int m1   = max(len, __shfl_xor_sync(0xffffffffu, len, 8));
    int mlen = max(m1,  __shfl_xor_sync(0xffffffffu, m1, 16));

    const __half2 z2 = __float2half2_rn(0.f);

    for (int b = 0; b < mlen; b += 16) {
        int idx0 = start + b + li;
        int idx1 = idx0 + 8;
        int2 e0 = (idx0 < end) ? g_csr[idx0] : make_int2(0, 0);
        int2 e1 = (idx1 < end) ? g_csr[idx1] : make_int2(0, 0);
        se[wid][g][li]     = e0;
        se[wid][g][li + 8] = e1;
        __syncwarp();

        __half2 a0 = z2, a1 = z2, a2 = z2, a3 = z2;   // even slots
        __half2 c0 = z2, c1 = z2, c2 = z2, c3 = z2;   // odd slots
#pragma unroll
        for (int j = 0; j < 16; j++) {                // fixed trip: batched LDGs
            int2    ej = se[wid][g][j];
            __half2 wj = *reinterpret_cast<__half2*>(&ej.y);
            uint4   t  = __ldg((const uint4*)(hin + ej.x + li * 4));
            __half2 t0 = *(__half2*)&t.x, t1 = *(__half2*)&t.y;
            __half2 t2 = *(__half2*)&t.z, t3 = *(__half2*)&t.w;
            if (j & 1) {
                c0 = __hfma2(wj, t0, c0); c1 = __hfma2(wj, t1, c1);
                c2 = __hfma2(wj, t2, c2); c3 = __hfma2(wj, t3, c3);
            } else {
                a0 = __hfma2(wj, t0, a0); a1 = __hfma2(wj, t1, a1);
                a2 = __hfma2(wj, t2, a2); a3 = __hfma2(wj, t3, a3);
            }
        }
        __syncwarp();

        float2 s0 = __half22float2(__hadd2(a0, c0));
        float2 s1 = __half22float2(__hadd2(a1, c1));
        float2 s2 = __half22float2(__hadd2(a2, c2));
        float2 s3 = __half22float2(__hadd2(a3, c3));
        accf[0] += s0.x; accf[1] += s0.y;
        accf[2] += s1.x; accf[3] += s1.y;
        accf[4] += s2.x; accf[5] += s2.y;
        accf[6] += s3.x; accf[7] += s3.y;
    }

    __half2 r0 = __floats2half2_rn(accf[0], accf[1]);
    __half2 r1 = __floats2half2_rn(accf[2], accf[3]);
    __half2 r2 = __floats2half2_rn(accf[4], accf[5]);
    __half2 r3 = __floats2half2_rn(accf[6], accf[7]);
    uint4 o;
    o.x = *(unsigned*)&r0; o.y = *(unsigned*)&r1;
    o.z = *(unsigned*)&r2; o.w = *(unsigned*)&r3;
    *(uint4*)(hout + row32 + li * 4) = o;
}

// ---------------- fused MLP on tensor cores (wmma m16n16k16, f32 accum) ----
#define LDA 72   // fp16 lds (mult of 8)
#define LDB 48   // W2 cols padded
__global__ void __launch_bounds__(256) k_mlp(const float* __restrict__ W1,
                                             const float* __restrict__ b1,
                                             const float* __restrict__ W2,
                                             const float* __restrict__ b2,
                                             float* __restrict__ out) {
    __shared__ __align__(16) __half AsH[32 * LDA];    // 4.6 KB
    __shared__ __align__(16) __half W1cH[64 * LDA];   // 9.2 KB
    __shared__ __align__(16) float  HsF[32 * LDA];    // 9.2 KB
    __shared__ __align__(16) __half HsH[32 * LDA];    // 4.6 KB
    __shared__ __align__(16) __half W2cH[64 * LDB];   // 6.1 KB
    __shared__ __align__(16) float  OutF[32 * LDB];   // 6.1 KB

    int tid = threadIdx.x;
    int wid = tid >> 5;
    int rb  = blockIdx.x * 32;        // NN divisible by 32

    const float inv = 1.0f / (NITER + 1);
    const size_t NN32 = (size_t)NN * (NF / 2);
    for (int l = tid; l < 32 * 16; l += 256) {   // quads of 4 feats
        int rr = l >> 4, q = l & 15;
        float4 s = make_float4(0.f, 0.f, 0.f, 0.f);
#pragma unroll
        for (int b = 0; b <= NITER; b++) {
            const uint2* hb = (const uint2*)(g_hh + (size_t)b * NN32);
            uint2 v = __ldg(&hb[(size_t)(rb + rr) * 16 + q]);
            float2 f0 = __half22float2(*(__half2*)&v.x);
            float2 f1 = __half22float2(*(__half2*)&v.y);
            s.x += f0.x; s.y += f0.y; s.z += f1.x; s.w += f1.y;
        }
        __half2 p0 = __floats2half2_rn(s.x * inv, s.y * inv);
        __half2 p1 = __floats2half2_rn(s.z * inv, s.w * inv);
        *(uint2*)&AsH[rr * LDA + q * 4] =
            make_uint2(*(unsigned*)&p0, *(unsigned*)&p1);
    }

    wmma::fragment<wmma::accumulator, 16, 16, 16, float> ofrag;
    int omi = wid / 3, oni = wid % 3;   // warps 0..5: out tile (omi, oni)
    if (wid < 6) wmma::fill_fragment(ofrag, 0.f);

    for (int c = 0; c < 4; c++) {
        __syncthreads();
        for (int l = tid; l < 64 * 64; l += 256) {
            int kk = l >> 6, j = l & 63;
            W1cH[kk * LDA + j] = __float2half(__ldg(&W1[kk * NH + c * 64 + j]));
        }
        for (int l = tid; l < 64 * LDB; l += 256) {
            int kk = l / LDB, n = l % LDB;
            W2cH[kk * LDB + n] =
                (n < NC) ? __float2half(__ldg(&W2[(c * 64 + kk) * NC + n]))
                         : __half(0.f);
        }
        __syncthreads();

        {
            int mi = wid >> 2, ni = wid & 3;
            wmma::fragment<wmma::accumulator, 16, 16, 16, float> hfrag;
            wmma::fill_fragment(hfrag, 0.f);
#pragma unroll
            for (int k = 0; k < 4; k++) {
                wmma::fragment<wmma::matrix_a, 16, 16, 16, __half, wmma::row_major> af;
                wmma::fragment<wmma::matrix_b, 16, 16, 16, __half, wmma::row_major> bf;
                wmma::load_matrix_sync(af, &AsH[mi * 16 * LDA + k * 16], LDA);
                wmma::load_matrix_sync(bf, &W1cH[k * 16 * LDA + ni * 16], LDA);
                wmma::mma_sync(hfrag, af, bf, hfrag);
            }
            wmma::store_matrix_sync(&HsF[mi * 16 * LDA + ni * 16], hfrag, LDA,
                                    wmma::mem_row_major);
        }
        __syncthreads();

        for (int l = tid; l < 32 * 64; l += 256) {
            int r = l >> 6, j = l & 63;
            float v = HsF[r * LDA + j] + __ldg(&b1[c * 64 + j]);
            HsH[r * LDA + j] = __float2half(fmaxf(v, 0.f));
        }
        __syncthreads();

        if (wid < 6) {
#pragma unroll
            for (int k = 0; k < 4; k++) {
                wmma::fragment<wmma::matrix_a, 16, 16, 16, __half, wmma::row_major> af;
                wmma::fragment<wmma::matrix_b, 16, 16, 16, __half, wmma::row_major> bf;
                wmma::load_matrix_sync(af, &HsH[omi * 16 * LDA + k * 16], LDA);
                wmma::load_matrix_sync(bf, &W2cH[k * 16 * LDB + oni * 16], LDB);
                wmma::mma_sync(ofrag, af, bf, ofrag);
            }
        }
    }

    __syncthreads();
    if (wid < 6)
        wmma::store_matrix_sync(&OutF[omi * 16 * LDB + oni * 16], ofrag, LDB,
                                wmma::mem_row_major);
    __syncthreads();

    for (int l = tid; l < 32 * NC; l += 256) {
        int r = l / NC, n = l - r * NC;
        out[(size_t)(rb + r) * NC + n] = OutF[r * LDB + n] + __ldg(&b2[n]);
    }
}

// ---------------- launch ----------------
extern "C" void kernel_launch(void* const* d_in, const int* in_sizes, int n_in,
                              void* d_out, int out_size) {
    const float* x   = (const float*)d_in[0];
    const int*   ei  = (const int*)d_in[1];   // int32 (JAX demotes int64)
    const float* W1  = (const float*)d_in[2];
    const float* b1  = (const float*)d_in[3];
    const float* W2  = (const float*)d_in[4];
    const float* b2  = (const float*)d_in[5];
    float*       out = (float*)d_out;

    int init_blocks = (NN * (NF / 4) + 511) / 512;   // 3125

    k_hist<<<(NE + 255) / 256, 256>>>(ei);                     // launch 1
    k_scan_init<<<NSCAN + init_blocks, 512>>>(x);              // launch 2
    k_degscan<<<1, NDEG>>>();                                  // launch 3
    k_scatter<<<(NE + 255) / 256, 256>>>(ei);                  // launch 4

    for (int it = 0; it < NITER; it++)                         // launches 5..12
        k_spmm<<<NN / 32, 256>>>(it);

    k_mlp<<<NN / 32, 256>>>(W1, b1, W2, b2, out);              // launch 13
}

// round 16
// speedup vs baseline: 1.0570x; 1.0061x over previous
#include <cuda_runtime.h>
#include <cuda_fp16.h>
#include <mma.h>

using namespace nvcuda;

#define NN 100000
#define NE 1200000
#define NCSR (NE + NN)                // edges + self-loops
#define NF 64
#define NH 256
#define NC 40
#define NITER 8
#define NSCAN 196                     // ceil(NN/512) scan tiles
#define NDEG 1024                     // degree bins for counting sort

// ---------------- scratch (device globals; no allocation) ----------------
__device__ int   g_cnt[NN];
__device__ float g_dinv[NN];
__device__ int   g_rowptr[NN + 1];
__device__ int   g_rank[NE];          // within-row rank of each edge (from hist)
__device__ int   g_degcnt[NDEG];
__device__ int   g_degoff[NDEG];
__device__ unsigned long long g_tile_state[NSCAN];  // (status<<32)|sum; 1=agg,2=prefix
__device__ int   g_tile_counter;
__device__ int   g_scan_done;
__device__ __align__(16) int4    g_task[NN];        // {start, len, row*32, 0} DESC degree
__device__ __align__(16) int2    g_csr[NCSR];       // {col*32, w as half2 bits}
// h0..h8 in fp16: (9 * 100000 * 32) half2 = 115 MB. Row = 32 half2 = 128 B.
__device__ __align__(16) __half2 g_hh[(NITER + 1) * (size_t)NN * (NF / 2)];

__device__ __forceinline__ int clampN(int v) {
    return min(max(v, 0), NN - 1);
}

// ---------------- L1: histogram + rank capture (+ reset per-run state) -----
// Invariant: g_cnt zero on entry (zeroed at load; re-zeroed by k_scatter).
// The atomic's return value is the edge's within-row rank -> scatter needs
// no atomics.
__global__ void k_hist(const int* __restrict__ ei) {
    int e = blockIdx.x * blockDim.x + threadIdx.x;
    if (e < NE) {
        int r = clampN(ei[e]);
        g_rank[e] = atomicAdd(&g_cnt[r], 1);
    }
    if (e < NSCAN) g_tile_state[e] = 0ULL;
    if (e < NDEG)  g_degcnt[e] = 0;
    if (e == NSCAN) { g_tile_counter = 0; g_scan_done = 0; }
}

// ---------------- L2: lookback scan + dinv + deg-hist + h0 init ------------
// The LAST scan tile to finish also scans the 1024 degree bins (pair-sum +
// 512-thread Hillis-Steele) -> k_degscan launch eliminated.
__global__ void __launch_bounds__(512) k_scan_init(const float* __restrict__ x) {
    __shared__ int s[512];
    __shared__ int spair[512];
    __shared__ int stile;
    __shared__ int sprefix;
    __shared__ int slast;

    if (blockIdx.x < NSCAN) {
        int t = threadIdx.x;
        if (t == 0) stile = atomicAdd(&g_tile_counter, 1);
        __syncthreads();
        int tile = stile;
        int i = tile * 512 + t;
        int deg = (i < NN) ? g_cnt[i] : 0;
        int v   = (i < NN) ? deg + 1 : 0;     // +1 self-loop slot
        if (i < NN) {
            g_dinv[i] = rsqrtf((float)(deg + 1));
            atomicAdd(&g_degcnt[min(deg, NDEG - 1)], 1);
        }
        s[t] = v;
        __syncthreads();
        for (int off = 1; off < 512; off <<= 1) {
            int add = (t >= off) ? s[t - off] : 0;
            __syncthreads();
            s[t] += add;
            __syncthreads();
        }
        int incl = s[t];
        int agg  = s[511];
        if (t == 0) {
            if (tile == 0) {
                atomicExch(&g_tile_state[0], (2ULL << 32) | (unsigned)agg);
                sprefix = 0;
            } else {
                atomicExch(&g_tile_state[tile], (1ULL << 32) | (unsigned)agg);
                int pre = 0;
                for (int p = tile - 1; p >= 0; ) {
                    unsigned long long st;
                    do { st = atomicAdd(&g_tile_state[p], 0ULL); } while ((st >> 32) == 0);
                    pre += (int)(unsigned)st;
                    if ((st >> 32) == 2ULL) break;
                    p--;
                }
                atomicExch(&g_tile_state[tile], (2ULL << 32) | (unsigned)(pre + agg));
                sprefix = pre;
            }
        }
        __syncthreads();
        if (i < NN) g_rowptr[i] = sprefix + incl - v;   // exclusive
        if (tile == 0 && t == 0) g_rowptr[NN] = NCSR;

        // last-finishing tile scans the degree bins
        __syncthreads();
        if (t == 0) {
            __threadfence();
            slast = (atomicAdd(&g_scan_done, 1) == NSCAN - 1) ? 1 : 0;
        }
        __syncthreads();
        if (slast) {
            int v0 = g_degcnt[2 * t];
            int v1 = g_degcnt[2 * t + 1];
            spair[t] = v0 + v1;
            __syncthreads();
            for (int off = 1; off < 512; off <<= 1) {
                int add = (t >= off) ? spair[t - off] : 0;
                __syncthreads();
                spair[t] += add;
                __syncthreads();
            }
            int excl = spair[t] - (v0 + v1);
            g_degoff[2 * t]     = excl;
            g_degoff[2 * t + 1] = excl + v0;
        }
    } else {
        int i = (blockIdx.x - NSCAN) * 512 + threadIdx.x;   // quad of 4 floats
        if (i < NN * (NF / 4)) {
            float4 v = ((const float4*)x)[i];
            __half2 a = __floats2half2_rn(v.x * 0.5f, v.y * 0.5f);
            __half2 b = __floats2half2_rn(v.z * 0.5f, v.w * 0.5f);
            *(uint2*)&g_hh[(size_t)i * 2] =
                make_uint2(*(unsigned*)&a, *(unsigned*)&b);
        }
    }
}

// ---------------- L3: scatter (atomic-free CSR) + tasks + re-zero ----------
// Edge position = rowptr[r] + rank[e]; self-loop in the row's last slot.
// Tasks written in DESCENDING degree order.
__global__ void k_scatter(const int* __restrict__ ei) {
    int e = blockIdx.x * blockDim.x + threadIdx.x;
    if (e < NE) {
        int r = clampN(ei[e]);
        int c = clampN(ei[NE + e]);
        int pos = g_rowptr[r] + g_rank[e];
        __half2 wh = __float2half2_rn(g_dinv[r] * g_dinv[c]);
        g_csr[pos] = make_int2(c * 32, *reinterpret_cast<int*>(&wh));
    }
    if (e < NN) {
        int deg = g_cnt[e];
        float dr = g_dinv[e];
        __half2 wh = __float2half2_rn(dr * dr);
        int start = g_rowptr[e];
        g_csr[start + deg] = make_int2(e * 32, *reinterpret_cast<int*>(&wh));
        int p = atomicAdd(&g_degoff[min(deg, NDEG - 1)], 1);
        g_task[NN - 1 - p] = make_int4(start, deg + 1, e * 32, 0);  // descending
        g_cnt[e] = 0;
    }
}

// ---------------- SPMM: h_{it+1} = A_norm h_it ------------------------------
// (R13 variant — best measured.) 4 rows/warp (degree-sorted tasks), 8-lane
// group per row, lane = 8 features (uint4). Fixed 16-iter inner loop.
__global__ void __launch_bounds__(256) k_spmm(int it) {
    const size_t NN32 = (size_t)NN * (NF / 2);
    const __half2* __restrict__ hin = g_hh + (size_t)it * NN32;
    __half2* __restrict__ hout      = g_hh + (size_t)(it + 1) * NN32;

    __shared__ int2 se[8][4][17];    // [warp][group][slot], padded

    int lane = threadIdx.x & 31;
    int wid  = threadIdx.x >> 5;
    int g    = lane >> 3;            // group 0..3
    int li   = lane & 7;             // lane in group

    int4 task = __ldg(&g_task[(blockIdx.x * 8 + wid) * 4 + g]);  // NN div by 32
    int start = task.x;
    int len   = task.y;
    int end   = start + len;
    int row32 = task.z;

    float accf[8] = {0.f, 0.f, 0.f, 0.f, 0.f, 0.f, 0.f, 0.f};

    int m1   = max(len, __shfl_xor_sync(0xffffffffu, len, 8));
    int mlen = max(m1,  __shfl_xor_sync(0xffffffffu, m1, 16));

    const __half2 z2 = __float2half2_rn(0.f);

    for (int b = 0; b < mlen; b += 16) {
        int idx0 = start + b + li;
        int idx1 = idx0 + 8;
        int2 e0 = (idx0 < end) ? g_csr[idx0] : make_int2(0, 0);
        int2 e1 = (idx1 < end) ? g_csr[idx1] : make_int2(0, 0);
        se[wid][g][li]     = e0;
        se[wid][g][li + 8] = e1;
        __syncwarp();

        __half2 a0 = z2, a1 = z2, a2 = z2, a3 = z2;   // even slots
        __half2 c0 = z2, c1 = z2, c2 = z2, c3 = z2;   // odd slots
#pragma unroll
        for (int j = 0; j < 16; j++) {                // fixed trip: batched LDGs
            int2    ej = se[wid][g][j];
            __half2 wj = *reinterpret_cast<__half2*>(&ej.y);
            uint4   t  = __ldg((const uint4*)(hin + ej.x + li * 4));
            __half2 t0 = *(__half2*)&t.x, t1 = *(__half2*)&t.y;
            __half2 t2 = *(__half2*)&t.z, t3 = *(__half2*)&t.w;
            if (j & 1) {
                c0 = __hfma2(wj, t0, c0); c1 = __hfma2(wj, t1, c1);
                c2 = __hfma2(wj, t2, c2); c3 = __hfma2(wj, t3, c3);
            } else {
                a0 = __hfma2(wj, t0, a0); a1 = __hfma2(wj, t1, a1);
                a2 = __hfma2(wj, t2, a2); a3 = __hfma2(wj, t3, a3);
            }
        }
        __syncwarp();

        float2 s0 = __half22float2(__hadd2(a0, c0));
        float2 s1 = __half22float2(__hadd2(a1, c1));
        float2 s2 = __half22float2(__hadd2(a2, c2));
        float2 s3 = __half22float2(__hadd2(a3, c3));
        accf[0] += s0.x; accf[1] += s0.y;
        accf[2] += s1.x; accf[3] += s1.y;
        accf[4] += s2.x; accf[5] += s2.y;
        accf[6] += s3.x; accf[7] += s3.y;
    }

    __half2 r0 = __floats2half2_rn(accf[0], accf[1]);
    __half2 r1 = __floats2half2_rn(accf[2], accf[3]);
    __half2 r2 = __floats2half2_rn(accf[4], accf[5]);
    __half2 r3 = __floats2half2_rn(accf[6], accf[7]);
    uint4 o;
    o.x = *(unsigned*)&r0; o.y = *(unsigned*)&r1;
    o.z = *(unsigned*)&r2; o.w = *(unsigned*)&r3;
    *(uint4*)(hout + row32 + li * 4) = o;
}

// ---------------- fused MLP on tensor cores (wmma m16n16k16, f32 accum) ----
#define LDA 72   // fp16 lds (mult of 8)
#define LDB 48   // W2 cols padded
__global__ void __launch_bounds__(256) k_mlp(const float* __restrict__ W1,
                                             const float* __restrict__ b1,
                                             const float* __restrict__ W2,
                                             const float* __restrict__ b2,
                                             float* __restrict__ out) {
    __shared__ __align__(16) __half AsH[32 * LDA];    // 4.6 KB
    __shared__ __align__(16) __half W1cH[64 * LDA];   // 9.2 KB
    __shared__ __align__(16) float  HsF[32 * LDA];    // 9.2 KB
    __shared__ __align__(16) __half HsH[32 * LDA];    // 4.6 KB
    __shared__ __align__(16) __half W2cH[64 * LDB];   // 6.1 KB
    __shared__ __align__(16) float  OutF[32 * LDB];   // 6.1 KB

    int tid = threadIdx.x;
    int wid = tid >> 5;
    int rb  = blockIdx.x * 32;        // NN divisible by 32

    const float inv = 1.0f / (NITER + 1);
    const size_t NN32 = (size_t)NN * (NF / 2);
    for (int l = tid; l < 32 * 16; l += 256) {   // quads of 4 feats
        int rr = l >> 4, q = l & 15;
        float4 s = make_float4(0.f, 0.f, 0.f, 0.f);
#pragma unroll
        for (int b = 0; b <= NITER; b++) {
            const uint2* hb = (const uint2*)(g_hh + (size_t)b * NN32);
            uint2 v = __ldg(&hb[(size_t)(rb + rr) * 16 + q]);
            float2 f0 = __half22float2(*(__half2*)&v.x);
            float2 f1 = __half22float2(*(__half2*)&v.y);
            s.x += f0.x; s.y += f0.y; s.z += f1.x; s.w += f1.y;
        }
        __half2 p0 = __floats2half2_rn(s.x * inv, s.y * inv);
        __half2 p1 = __floats2half2_rn(s.z * inv, s.w * inv);
        *(uint2*)&AsH[rr * LDA + q * 4] =
            make_uint2(*(unsigned*)&p0, *(unsigned*)&p1);
    }

    wmma::fragment<wmma::accumulator, 16, 16, 16, float> ofrag;
    int omi = wid / 3, oni = wid % 3;   // warps 0..5: out tile (omi, oni)
    if (wid < 6) wmma::fill_fragment(ofrag, 0.f);

    for (int c = 0; c < 4; c++) {
        __syncthreads();
        for (int l = tid; l < 64 * 64; l += 256) {
            int kk = l >> 6, j = l & 63;
            W1cH[kk * LDA + j] = __float2half(__ldg(&W1[kk * NH + c * 64 + j]));
        }
        for (int l = tid; l < 64 * LDB; l += 256) {
            int kk = l / LDB, n = l % LDB;
            W2cH[kk * LDB + n] =
                (n < NC) ? __float2half(__ldg(&W2[(c * 64 + kk) * NC + n]))
                         : __half(0.f);
        }
        __syncthreads();

        {
            int mi = wid >> 2, ni = wid & 3;
            wmma::fragment<wmma::accumulator, 16, 16, 16, float> hfrag;
            wmma::fill_fragment(hfrag, 0.f);
#pragma unroll
            for (int k = 0; k < 4; k++) {
                wmma::fragment<wmma::matrix_a, 16, 16, 16, __half, wmma::row_major> af;
                wmma::fragment<wmma::matrix_b, 16, 16, 16, __half, wmma::row_major> bf;
                wmma::load_matrix_sync(af, &AsH[mi * 16 * LDA + k * 16], LDA);
                wmma::load_matrix_sync(bf, &W1cH[k * 16 * LDA + ni * 16], LDA);
                wmma::mma_sync(hfrag, af, bf, hfrag);
            }
            wmma::store_matrix_sync(&HsF[mi * 16 * LDA + ni * 16], hfrag, LDA,
                                    wmma::mem_row_major);
        }
        __syncthreads();

        for (int l = tid; l < 32 * 64; l += 256) {
            int r = l >> 6, j = l & 63;
            float v = HsF[r * LDA + j] + __ldg(&b1[c * 64 + j]);
            HsH[r * LDA + j] = __float2half(fmaxf(v, 0.f));
        }
        __syncthreads();

        if (wid < 6) {
#pragma unroll
            for (int k = 0; k < 4; k++) {
                wmma::fragment<wmma::matrix_a, 16, 16, 16, __half, wmma::row_major> af;
                wmma::fragment<wmma::matrix_b, 16, 16, 16, __half, wmma::row_major> bf;
                wmma::load_matrix_sync(af, &HsH[omi * 16 * LDA + k * 16], LDA);
                wmma::load_matrix_sync(bf, &W2cH[k * 16 * LDB + oni * 16], LDB);
                wmma::mma_sync(ofrag, af, bf, ofrag);
            }
        }
    }

    __syncthreads();
    if (wid < 6)
        wmma::store_matrix_sync(&OutF[omi * 16 * LDB + oni * 16], ofrag, LDB,
                                wmma::mem_row_major);
    __syncthreads();

    for (int l = tid; l < 32 * NC; l += 256) {
        int r = l / NC, n = l - r * NC;
        out[(size_t)(rb + r) * NC + n] = OutF[r * LDB + n] + __ldg(&b2[n]);
    }
}

// ---------------- launch ----------------
extern "C" void kernel_launch(void* const* d_in, const int* in_sizes, int n_in,
                              void* d_out, int out_size) {
    const float* x   = (const float*)d_in[0];
    const int*   ei  = (const int*)d_in[1];   // int32 (JAX demotes int64)
    const float* W1  = (const float*)d_in[2];
    const float* b1  = (const float*)d_in[3];
    const float* W2  = (const float*)d_in[4];
    const float* b2  = (const float*)d_in[5];
    float*       out = (float*)d_out;

    int init_blocks = (NN * (NF / 4) + 511) / 512;   // 3125

    k_hist<<<(NE + 255) / 256, 256>>>(ei);                     // launch 1
    k_scan_init<<<NSCAN + init_blocks, 512>>>(x);              // launch 2 (incl. degscan)
    k_scatter<<<(NE + 255) / 256, 256>>>(ei);                  // launch 3

    for (int it = 0; it < NITER; it++)                         // launches 4..11
        k_spmm<<<NN / 32, 256>>>(it);

    k_mlp<<<NN / 32, 256>>>(W1, b1, W2, b2, out);              // launch 12
}